// round 11
// baseline (speedup 1.0000x reference)
#include <cuda_runtime.h>
#include <cuda_bf16.h>
#include <cuda_fp16.h>
#include <math.h>
#include <stdint.h>

#define N_NODES 50000
#define N_EDGES 1600000
#define IN_DIM 512
#define HID_DIM 256
#define OUT_DIM 64
#define K_HOPS 4
#define ALPHA 0.1f

#define SCAN_BLK 1024
#define SCAN_NBLK ((N_NODES + SCAN_BLK - 1) / SCAN_BLK)   // 49

// ---------------- device scratch (no allocs allowed) ----------------
__device__ __half  g_h16[(size_t)N_NODES * IN_DIM];
__device__ __half  g_w1[IN_DIM * HID_DIM];
__device__ __half  g_w2[HID_DIM * OUT_DIM];
__device__ __half  g_hid16[(size_t)N_NODES * HID_DIM];
__device__ __half  g_x016[(size_t)N_NODES * OUT_DIM];   // feat0 fp16 (unscaled)
__device__ __half  g_x0s[(size_t)N_NODES * OUT_DIM];    // feat0 * nsrc
__device__ __half  g_fA16[(size_t)N_NODES * OUT_DIM];
__device__ __half  g_fAs[(size_t)N_NODES * OUT_DIM];
__device__ __half  g_fB16[(size_t)N_NODES * OUT_DIM];
__device__ __half  g_fBs[(size_t)N_NODES * OUT_DIM];
__device__ int   g_deg_out[N_NODES];
__device__ int   g_deg_in[N_NODES];
__device__ int   g_fill[N_NODES];
__device__ int   g_row_ptr[N_NODES + 1];
__device__ float g_nsrc[N_NODES];
__device__ float g_ndst[N_NODES];
__device__ int   g_csr_src[N_EDGES];
__device__ float g_es[N_NODES];
__device__ float g_ed[N_NODES];
__device__ float g_m[N_NODES];
__device__ float g_is[N_NODES];
__device__ int   g_bsum[SCAN_NBLK];
__device__ int   g_boff[SCAN_NBLK];

// ---------------- conversion kernel ----------------
__global__ void f32_to_f16_kernel(const float* __restrict__ in,
                                  __half* __restrict__ out, int n4) {
    int i = blockIdx.x * blockDim.x + threadIdx.x;
    if (i < n4) {
        float4 v = ((const float4*)in)[i];
        __half2 a = __floats2half2_rn(v.x, v.y);
        __half2 b = __floats2half2_rn(v.z, v.w);
        uint2 u;
        u.x = *(uint32_t*)&a;
        u.y = *(uint32_t*)&b;
        ((uint2*)out)[i] = u;
    }
}

// ---------------- small kernels ----------------
__global__ void zero3_kernel() {
    int i = blockIdx.x * blockDim.x + threadIdx.x;
    if (i < N_NODES) {
        g_deg_out[i] = 0;
        g_deg_in[i]  = 0;
        g_fill[i]    = 0;
    }
}

__global__ void count_deg_kernel(const int* __restrict__ src, const int* __restrict__ dst) {
    int e = blockIdx.x * blockDim.x + threadIdx.x;
    if (e < N_EDGES) {
        atomicAdd(&g_deg_out[src[e]], 1);
        atomicAdd(&g_deg_in[dst[e]], 1);
    }
}

__global__ void norm_kernel() {
    int i = blockIdx.x * blockDim.x + threadIdx.x;
    if (i < N_NODES) {
        int doo = g_deg_out[i]; if (doo < 1) doo = 1;
        int din = g_deg_in[i];  if (din < 1) din = 1;
        g_nsrc[i] = rsqrtf((float)doo);
        g_ndst[i] = rsqrtf((float)din);
    }
}

// ---- 3-phase grid-wide exclusive scan of g_deg_in -> g_row_ptr ----
__global__ void scan1_kernel() {
    __shared__ int warpsum[32];
    int tid = threadIdx.x, lane = tid & 31, wid = tid >> 5;
    int i = blockIdx.x * SCAN_BLK + tid;
    int v = (i < N_NODES) ? g_deg_in[i] : 0;
    int x = v;
    #pragma unroll
    for (int off = 1; off < 32; off <<= 1) {
        int t = __shfl_up_sync(0xffffffffu, x, off);
        if (lane >= off) x += t;
    }
    if (lane == 31) warpsum[wid] = x;
    __syncthreads();
    if (wid == 0) {
        int w = warpsum[lane];
        #pragma unroll
        for (int off = 1; off < 32; off <<= 1) {
            int t = __shfl_up_sync(0xffffffffu, w, off);
            if (lane >= off) w += t;
        }
        warpsum[lane] = w;
    }
    __syncthreads();
    int offset = (wid > 0) ? warpsum[wid - 1] : 0;
    if (i < N_NODES) g_row_ptr[i] = x + offset - v;
    if (tid == SCAN_BLK - 1) g_bsum[blockIdx.x] = x + offset;
}

__global__ void scan2_kernel() {
    int lane = threadIdx.x;
    int carry = 0;
    for (int base = 0; base < SCAN_NBLK; base += 32) {
        int i = base + lane;
        int v = (i < SCAN_NBLK) ? g_bsum[i] : 0;
        int x = v;
        #pragma unroll
        for (int off = 1; off < 32; off <<= 1) {
            int t = __shfl_up_sync(0xffffffffu, x, off);
            if (lane >= off) x += t;
        }
        if (i < SCAN_NBLK) g_boff[i] = carry + x - v;
        carry += __shfl_sync(0xffffffffu, x, 31);
    }
    if (lane == 0) g_row_ptr[N_NODES] = carry;
}

__global__ void scan3_kernel() {
    int i = blockIdx.x * SCAN_BLK + threadIdx.x;
    if (i < N_NODES && blockIdx.x > 0) g_row_ptr[i] += g_boff[blockIdx.x];
}

__global__ void build_csr_kernel(const int* __restrict__ src, const int* __restrict__ dst) {
    int e = blockIdx.x * blockDim.x + threadIdx.x;
    if (e < N_EDGES) {
        int d = dst[e];
        int pos = g_row_ptr[d] + atomicAdd(&g_fill[d], 1);
        g_csr_src[pos] = src[e];
    }
}

// ---------------- fp16 tensor-core GEMM, 4-stage cp.async, static smem ---
__device__ __forceinline__ uint32_t smem_u32(const void* p) {
    return (uint32_t)__cvta_generic_to_shared(p);
}
__device__ __forceinline__ void cp_async16(uint32_t s, const void* g) {
    asm volatile("cp.async.cg.shared.global [%0], [%1], 16;\n"
        :: "r"(s), "l"(__cvta_generic_to_global(g)));
}
__device__ __forceinline__ void cp_commit() {
    asm volatile("cp.async.commit_group;\n");
}
template <int NW>
__device__ __forceinline__ void cp_wait() {
    asm volatile("cp.async.wait_group %0;\n" :: "n"(NW));
}
__device__ __forceinline__ void ldsm_x4(uint32_t* r, uint32_t addr) {
    asm volatile("ldmatrix.sync.aligned.m8n8.x4.shared.b16 {%0,%1,%2,%3}, [%4];\n"
        : "=r"(r[0]), "=r"(r[1]), "=r"(r[2]), "=r"(r[3]) : "r"(addr));
}
__device__ __forceinline__ void ldsm_x4_trans(uint32_t* r, uint32_t addr) {
    asm volatile("ldmatrix.sync.aligned.m8n8.x4.trans.shared.b16 {%0,%1,%2,%3}, [%4];\n"
        : "=r"(r[0]), "=r"(r[1]), "=r"(r[2]), "=r"(r[3]) : "r"(addr));
}
__device__ __forceinline__ void mma16816h(float* c, const uint32_t* a, const uint32_t* b) {
    asm volatile(
        "mma.sync.aligned.m16n8k16.row.col.f32.f16.f16.f32 "
        "{%0,%1,%2,%3}, {%4,%5,%6,%7}, {%8,%9}, {%0,%1,%2,%3};\n"
        : "+f"(c[0]), "+f"(c[1]), "+f"(c[2]), "+f"(c[3])
        : "r"(a[0]), "r"(a[1]), "r"(a[2]), "r"(a[3]), "r"(b[0]), "r"(b[1]));
}

#define GBM 128
#define GBK 16
#define GSTAGES 4

template <int BN, bool RELU, bool OUT16>
__global__ __launch_bounds__(256)
void gemm_f16_kernel(const __half* __restrict__ A,
                     const __half* __restrict__ B,
                     const float* __restrict__ bias,
                     float* __restrict__ Cf,
                     __half* __restrict__ C16,
                     int M, int N, int K) {
    constexpr int WN  = BN / 2;
    constexpr int NJ  = WN / 8;
    constexpr int NJP = NJ / 2;
    __shared__ __align__(16) __half As[GSTAGES][GBM][GBK + 8];
    __shared__ __align__(16) __half Bs[GSTAGES][GBK][BN + 8];

    int tid = threadIdx.x;
    int lane = tid & 31, wid = tid >> 5;
    int wm = wid & 3, wn = wid >> 2;
    int rowBase = blockIdx.y * GBM;
    int colBase = blockIdx.x * BN;

    float acc[2][NJ][4];
    #pragma unroll
    for (int i = 0; i < 2; i++)
        #pragma unroll
        for (int j = 0; j < NJ; j++)
            #pragma unroll
            for (int q = 0; q < 4; q++) acc[i][j][q] = 0.f;

    auto load_stage = [&](int s, int k0) {
        {
            int r = tid >> 1;
            int c8 = (tid & 1) << 3;
            int row = rowBase + r;
            if (row > M - 1) row = M - 1;
            cp_async16(smem_u32(&As[s][r][c8]), A + (size_t)row * K + k0 + c8);
        }
        #pragma unroll
        for (int q = tid; q < 2 * BN; q += 256) {
            int r = q / (BN / 8);
            int c8 = (q % (BN / 8)) << 3;
            cp_async16(smem_u32(&Bs[s][r][c8]), B + (size_t)(k0 + r) * N + colBase + c8);
        }
        cp_commit();
    };

    int T = K / GBK;
    load_stage(0, 0);
    load_stage(1, GBK);
    load_stage(2, 2 * GBK);

    for (int t = 0; t < T; t++) {
        cp_wait<GSTAGES - 2>();
        __syncthreads();
        int pf = t + GSTAGES - 1;
        if (pf < T) load_stage(pf % GSTAGES, pf * GBK);
        int cur = t % GSTAGES;

        uint32_t a[2][4];
        #pragma unroll
        for (int mi = 0; mi < 2; mi++) {
            int r = wm * 32 + mi * 16 + (lane & 15);
            int c = (lane >> 4) << 3;
            ldsm_x4(a[mi], smem_u32(&As[cur][r][c]));
        }
        uint32_t b[NJ][2];
        #pragma unroll
        for (int p = 0; p < NJP; p++) {
            int r = (lane & 7) + (lane & 8);
            int c = wn * WN + p * 16 + ((lane >> 4) << 3);
            uint32_t tt[4];
            ldsm_x4_trans(tt, smem_u32(&Bs[cur][r][c]));
            b[2 * p][0] = tt[0]; b[2 * p][1] = tt[1];
            b[2 * p + 1][0] = tt[2]; b[2 * p + 1][1] = tt[3];
        }
        #pragma unroll
        for (int mi = 0; mi < 2; mi++)
            #pragma unroll
            for (int nj = 0; nj < NJ; nj++)
                mma16816h(acc[mi][nj], a[mi], b[nj]);
    }

    int g = lane >> 2, tig = lane & 3;
    #pragma unroll
    for (int mi = 0; mi < 2; mi++) {
        int row0 = rowBase + wm * 32 + mi * 16 + g;
        int row1 = row0 + 8;
        #pragma unroll
        for (int nj = 0; nj < NJ; nj++) {
            int col = colBase + wn * WN + nj * 8 + 2 * tig;
            float bv0 = bias[col], bv1 = bias[col + 1];
            float v0 = acc[mi][nj][0] + bv0;
            float v1 = acc[mi][nj][1] + bv1;
            float v2 = acc[mi][nj][2] + bv0;
            float v3 = acc[mi][nj][3] + bv1;
            if (RELU) {
                v0 = fmaxf(v0, 0.f); v1 = fmaxf(v1, 0.f);
                v2 = fmaxf(v2, 0.f); v3 = fmaxf(v3, 0.f);
            }
            if (OUT16) {
                if (row0 < M) *(__half2*)&C16[(size_t)row0 * N + col] = __floats2half2_rn(v0, v1);
                if (row1 < M) *(__half2*)&C16[(size_t)row1 * N + col] = __floats2half2_rn(v2, v3);
            } else {
                if (row0 < M) {
                    Cf[(size_t)row0 * N + col]     = v0;
                    Cf[(size_t)row0 * N + col + 1] = v1;
                }
                if (row1 < M) {
                    Cf[(size_t)row1 * N + col]     = v2;
                    Cf[(size_t)row1 * N + col + 1] = v3;
                }
            }
        }
    }
}

// ------- pre-scale x0: x0s = x016 * nsrc (8 lanes/node, uint4) ------------
__global__ void scale_x0_kernel() {
    int i = blockIdx.x * blockDim.x + threadIdx.x;
    if (i >= N_NODES * 8) return;
    int node = i >> 3;
    float ns = g_nsrc[node];
    uint4 u = ((const uint4*)g_x016)[i];
    __half2* h = (__half2*)&u;
    uint4 o;
    __half2* ho = (__half2*)&o;
    #pragma unroll
    for (int q = 0; q < 4; q++) {
        float2 f = __half22float2(h[q]);
        ho[q] = __floats2half2_rn(f.x * ns, f.y * ns);
    }
    ((uint4*)g_x0s)[i] = o;
}

// ------- propagation hop: 8 lanes/node, pre-scaled input, pure gather-add -
__device__ __forceinline__ void acc8(float* a, uint4 u) {
    __half2* h = (__half2*)&u;
    #pragma unroll
    for (int q = 0; q < 4; q++) {
        float2 f = __half22float2(h[q]);
        a[2 * q]     += f.x;
        a[2 * q + 1] += f.y;
    }
}

__device__ __forceinline__ void gather_accum(const __half* __restrict__ fin_s,
                                             int beg, int end, int lane, float* a) {
    int p = beg;
    for (; p + 4 <= end; p += 4) {
        int s0 = g_csr_src[p];
        int s1 = g_csr_src[p + 1];
        int s2 = g_csr_src[p + 2];
        int s3 = g_csr_src[p + 3];
        uint4 u0 = ((const uint4*)(fin_s + (size_t)s0 * OUT_DIM))[lane];
        uint4 u1 = ((const uint4*)(fin_s + (size_t)s1 * OUT_DIM))[lane];
        uint4 u2 = ((const uint4*)(fin_s + (size_t)s2 * OUT_DIM))[lane];
        uint4 u3 = ((const uint4*)(fin_s + (size_t)s3 * OUT_DIM))[lane];
        acc8(a, u0); acc8(a, u1); acc8(a, u2); acc8(a, u3);
    }
    for (; p < end; p++) {
        int s = g_csr_src[p];
        acc8(a, ((const uint4*)(fin_s + (size_t)s * OUT_DIM))[lane]);
    }
}

__global__ void prop_kernel(const __half* __restrict__ fin_s,
                            __half* __restrict__ fout,
                            __half* __restrict__ fout_s) {
    int t = blockIdx.x * blockDim.x + threadIdx.x;
    int node = t >> 3;
    if (node >= N_NODES) return;
    int lane = t & 7;
    int beg = g_row_ptr[node], end = g_row_ptr[node + 1];
    float a[8] = {0.f, 0.f, 0.f, 0.f, 0.f, 0.f, 0.f, 0.f};
    gather_accum(fin_s, beg, end, lane, a);
    float nd = (1.f - ALPHA) * g_ndst[node];
    uint4 uz = ((const uint4*)(g_x016 + (size_t)node * OUT_DIM))[lane];
    __half2* hz = (__half2*)&uz;
    float o[8];
    #pragma unroll
    for (int q = 0; q < 4; q++) {
        float2 z = __half22float2(hz[q]);
        o[2 * q]     = a[2 * q] * nd + ALPHA * z.x;
        o[2 * q + 1] = a[2 * q + 1] * nd + ALPHA * z.y;
    }
    uint4 uo;
    __half2* ho = (__half2*)&uo;
    #pragma unroll
    for (int q = 0; q < 4; q++)
        ho[q] = __floats2half2_rn(o[2 * q], o[2 * q + 1]);
    ((uint4*)(fout + (size_t)node * OUT_DIM))[lane] = uo;
    float ns = g_nsrc[node];
    uint4 us;
    __half2* hs = (__half2*)&us;
    #pragma unroll
    for (int q = 0; q < 4; q++)
        hs[q] = __floats2half2_rn(o[2 * q] * ns, o[2 * q + 1] * ns);
    ((uint4*)(fout_s + (size_t)node * OUT_DIM))[lane] = us;
}

// ------- final hop fused with log_softmax output + attention dots ---------
__global__ void prop_final_kernel(const __half* __restrict__ fin_s,
                                  const float* __restrict__ wsrc,
                                  const float* __restrict__ wdst,
                                  float* __restrict__ out_lsm) {
    int t = blockIdx.x * blockDim.x + threadIdx.x;
    int node = t >> 3;
    if (node >= N_NODES) return;
    int lane = t & 7;
    int beg = g_row_ptr[node], end = g_row_ptr[node + 1];
    float a[8] = {0.f, 0.f, 0.f, 0.f, 0.f, 0.f, 0.f, 0.f};
    gather_accum(fin_s, beg, end, lane, a);
    float nd = (1.f - ALPHA) * g_ndst[node];
    uint4 uz = ((const uint4*)(g_x016 + (size_t)node * OUT_DIM))[lane];
    __half2* hz = (__half2*)&uz;
    float o[8];
    #pragma unroll
    for (int q = 0; q < 4; q++) {
        float2 z = __half22float2(hz[q]);
        o[2 * q]     = a[2 * q] * nd + ALPHA * z.x;
        o[2 * q + 1] = a[2 * q + 1] * nd + ALPHA * z.y;
    }

    // log_softmax over 64 features (reduce across the 8-lane octet)
    float m = o[0];
    #pragma unroll
    for (int q = 1; q < 8; q++) m = fmaxf(m, o[q]);
    #pragma unroll
    for (int off = 1; off < 8; off <<= 1)
        m = fmaxf(m, __shfl_xor_sync(0xffffffffu, m, off));
    float s = 0.f;
    #pragma unroll
    for (int q = 0; q < 8; q++) s += expf(o[q] - m);
    #pragma unroll
    for (int off = 1; off < 8; off <<= 1)
        s += __shfl_xor_sync(0xffffffffu, s, off);
    float lse = m + logf(s);
    float4 w0, w1;
    w0.x = o[0] - lse; w0.y = o[1] - lse; w0.z = o[2] - lse; w0.w = o[3] - lse;
    w1.x = o[4] - lse; w1.y = o[5] - lse; w1.z = o[6] - lse; w1.w = o[7] - lse;
    ((float4*)(out_lsm + (size_t)node * OUT_DIM))[lane * 2]     = w0;
    ((float4*)(out_lsm + (size_t)node * OUT_DIM))[lane * 2 + 1] = w1;

    // attention dots
    float4 a0 = ((const float4*)wsrc)[lane * 2];
    float4 a1 = ((const float4*)wsrc)[lane * 2 + 1];
    float4 b0 = ((const float4*)wdst)[lane * 2];
    float4 b1 = ((const float4*)wdst)[lane * 2 + 1];
    float es = o[0] * a0.x + o[1] * a0.y + o[2] * a0.z + o[3] * a0.w
             + o[4] * a1.x + o[5] * a1.y + o[6] * a1.z + o[7] * a1.w;
    float ed = o[0] * b0.x + o[1] * b0.y + o[2] * b0.z + o[3] * b0.w
             + o[4] * b1.x + o[5] * b1.y + o[6] * b1.z + o[7] * b1.w;
    #pragma unroll
    for (int off = 1; off < 8; off <<= 1) {
        es += __shfl_xor_sync(0xffffffffu, es, off);
        ed += __shfl_xor_sync(0xffffffffu, ed, off);
    }
    if (lane == 0) {
        g_es[node] = es;
        g_ed[node] = ed;
    }
}

// --------- attention phase 1: per-node max & inverse-sum (warp/node) ------
__global__ void attn1_kernel() {
    int node = (blockIdx.x * blockDim.x + threadIdx.x) >> 5;
    if (node >= N_NODES) return;
    int lane = threadIdx.x & 31;
    int beg = g_row_ptr[node], end = g_row_ptr[node + 1];
    int deg = end - beg;
    if (deg == 0) return;
    float edv = g_ed[node];

    if (deg <= 64) {
        int p0 = beg + lane, p1 = beg + 32 + lane;
        bool a0 = p0 < end, a1 = p1 < end;
        float e0 = a0 ? tanhf(g_es[g_csr_src[p0]] + edv) : -INFINITY;
        float e1 = a1 ? tanhf(g_es[g_csr_src[p1]] + edv) : -INFINITY;
        float m = fmaxf(e0, e1);
        #pragma unroll
        for (int off = 16; off; off >>= 1) m = fmaxf(m, __shfl_xor_sync(0xffffffffu, m, off));
        float s = (a0 ? expf(e0 - m) : 0.f) + (a1 ? expf(e1 - m) : 0.f);
        #pragma unroll
        for (int off = 16; off; off >>= 1) s += __shfl_xor_sync(0xffffffffu, s, off);
        if (lane == 0) {
            g_m[node] = m;
            g_is[node] = 1.f / s;
        }
        return;
    }

    float m = -INFINITY;
    for (int p = beg + lane; p < end; p += 32)
        m = fmaxf(m, tanhf(g_es[g_csr_src[p]] + edv));
    #pragma unroll
    for (int off = 16; off; off >>= 1) m = fmaxf(m, __shfl_xor_sync(0xffffffffu, m, off));
    float s = 0.f;
    for (int p = beg + lane; p < end; p += 32)
        s += expf(tanhf(g_es[g_csr_src[p]] + edv) - m);
    #pragma unroll
    for (int off = 16; off; off >>= 1) s += __shfl_xor_sync(0xffffffffu, s, off);
    if (lane == 0) {
        g_m[node] = m;
        g_is[node] = 1.f / s;
    }
}

// --------- attention phase 2: edge-parallel coalesced write ---------------
__global__ void attn2_kernel(const int* __restrict__ src, const int* __restrict__ dst,
                             float* __restrict__ attn_out) {
    int e = blockIdx.x * blockDim.x + threadIdx.x;
    if (e < N_EDGES) {
        int s = src[e];
        int d = dst[e];
        float v = tanhf(g_es[s] + g_ed[d]);
        attn_out[e] = expf(v - g_m[d]) * g_is[d];
    }
}

// ---------------- launch ----------------
extern "C" void kernel_launch(void* const* d_in, const int* in_sizes, int n_in,
                              void* d_out, int out_size) {
    const float* h   = (const float*)d_in[0];
    const int*   src = (const int*)d_in[1];
    const int*   dst = (const int*)d_in[2];
    const float* W1  = (const float*)d_in[3];
    const float* b1  = (const float*)d_in[4];
    const float* W2  = (const float*)d_in[5];
    const float* b2  = (const float*)d_in[6];
    const float* wsr = (const float*)d_in[7];
    const float* wds = (const float*)d_in[8];
    float* out = (float*)d_out;

    __half *p_h16, *p_w1, *p_w2, *p_hid16, *p_x016, *p_x0s, *p_fA, *p_fAs, *p_fB, *p_fBs;
    cudaGetSymbolAddress((void**)&p_h16, g_h16);
    cudaGetSymbolAddress((void**)&p_w1, g_w1);
    cudaGetSymbolAddress((void**)&p_w2, g_w2);
    cudaGetSymbolAddress((void**)&p_hid16, g_hid16);
    cudaGetSymbolAddress((void**)&p_x016, g_x016);
    cudaGetSymbolAddress((void**)&p_x0s, g_x0s);
    cudaGetSymbolAddress((void**)&p_fA, g_fA16);
    cudaGetSymbolAddress((void**)&p_fAs, g_fAs);
    cudaGetSymbolAddress((void**)&p_fB, g_fB16);
    cudaGetSymbolAddress((void**)&p_fBs, g_fBs);

    const int TPB = 256;
    int nodeBlocks = (N_NODES + TPB - 1) / TPB;
    int edgeBlocks = (N_EDGES + TPB - 1) / TPB;
    int warpNodeBlocks = (N_NODES * 32 + TPB - 1) / TPB;
    int octNodeBlocks = (N_NODES * 8 + TPB - 1) / TPB;

    // 1-3: zero + conversions (gemm1 kept in ncu capture slot 4)
    zero3_kernel<<<nodeBlocks, TPB>>>();
    {
        int n4 = N_NODES * IN_DIM / 4;
        f32_to_f16_kernel<<<(n4 + TPB - 1) / TPB, TPB>>>(h, p_h16, n4);
        int w4 = IN_DIM * HID_DIM / 4;
        f32_to_f16_kernel<<<(w4 + TPB - 1) / TPB, TPB>>>(W1, p_w1, w4);
    }

    // 4: GEMM1  hidden16 = fp16(relu(h @ W1 + b1)) — BN=64 tiles for occupancy
    {
        dim3 grid1(HID_DIM / 64, (N_NODES + GBM - 1) / GBM);
        gemm_f16_kernel<64, true, true><<<grid1, 256>>>(
            p_h16, p_w1, b1, nullptr, p_hid16, N_NODES, HID_DIM, IN_DIM);
    }

    {
        int w4 = HID_DIM * OUT_DIM / 4;
        f32_to_f16_kernel<<<(w4 + TPB - 1) / TPB, TPB>>>(W2, p_w2, w4);
    }
    count_deg_kernel<<<edgeBlocks, TPB>>>(src, dst);
    norm_kernel<<<nodeBlocks, TPB>>>();
    scan1_kernel<<<SCAN_NBLK, SCAN_BLK>>>();
    scan2_kernel<<<1, 32>>>();
    scan3_kernel<<<SCAN_NBLK, SCAN_BLK>>>();
    build_csr_kernel<<<edgeBlocks, TPB>>>(src, dst);

    // GEMM2  x0(fp16) = hidden @ W2 + b2, then pre-scale
    {
        dim3 grid2(OUT_DIM / 64, (N_NODES + GBM - 1) / GBM);
        gemm_f16_kernel<64, false, true><<<grid2, 256>>>(
            p_hid16, p_w2, b2, nullptr, p_x016, N_NODES, OUT_DIM, HID_DIM);
    }
    scale_x0_kernel<<<octNodeBlocks, TPB>>>();

    // K_HOPS=4 propagation; final hop fused with lsm output + dots
    prop_kernel<<<octNodeBlocks, TPB>>>(p_x0s, p_fA, p_fAs);
    prop_kernel<<<octNodeBlocks, TPB>>>(p_fAs, p_fB, p_fBs);
    prop_kernel<<<octNodeBlocks, TPB>>>(p_fBs, p_fA, p_fAs);
    prop_final_kernel<<<octNodeBlocks, TPB>>>(p_fAs, wsr, wds, out);

    // attention: per-node (m, 1/s), then edge-parallel coalesced write
    attn1_kernel<<<warpNodeBlocks, TPB>>>();
    attn2_kernel<<<edgeBlocks, TPB>>>(src, dst, out + (size_t)N_NODES * OUT_DIM);
}

// round 12
// speedup vs baseline: 1.0009x; 1.0009x over previous
#include <cuda_runtime.h>
#include <cuda_bf16.h>
#include <cuda_fp16.h>
#include <math.h>
#include <stdint.h>

#define N_NODES 50000
#define N_EDGES 1600000
#define IN_DIM 512
#define HID_DIM 256
#define OUT_DIM 64
#define K_HOPS 4
#define ALPHA 0.1f

#define SCAN_BLK 1024
#define SCAN_NBLK ((N_NODES + SCAN_BLK - 1) / SCAN_BLK)   // 49

// ---------------- device scratch (no allocs allowed) ----------------
__device__ __half  g_h16[(size_t)N_NODES * IN_DIM];
__device__ __half  g_w1[IN_DIM * HID_DIM];
__device__ __half  g_w2[HID_DIM * OUT_DIM];
__device__ __half  g_hid16[(size_t)N_NODES * HID_DIM];
__device__ __half  g_x016[(size_t)N_NODES * OUT_DIM];   // feat0 fp16 (unscaled)
__device__ __half  g_x0s[(size_t)N_NODES * OUT_DIM];    // feat0 * nsrc
__device__ __half  g_fA16[(size_t)N_NODES * OUT_DIM];
__device__ __half  g_fAs[(size_t)N_NODES * OUT_DIM];
__device__ __half  g_fB16[(size_t)N_NODES * OUT_DIM];
__device__ __half  g_fBs[(size_t)N_NODES * OUT_DIM];
__device__ int   g_deg_out[N_NODES];
__device__ int   g_deg_in[N_NODES];
__device__ int   g_fill[N_NODES];
__device__ int   g_row_ptr[N_NODES + 1];
__device__ float g_nsrc[N_NODES];
__device__ float g_ndst[N_NODES];
__device__ int   g_csr_src[N_EDGES];
__device__ float g_es[N_NODES];
__device__ float g_ed[N_NODES];
__device__ float g_m[N_NODES];
__device__ float g_is[N_NODES];
__device__ int   g_bsum[SCAN_NBLK];
__device__ int   g_boff[SCAN_NBLK];

// ---------------- conversion kernel ----------------
__global__ void f32_to_f16_kernel(const float* __restrict__ in,
                                  __half* __restrict__ out, int n4) {
    int i = blockIdx.x * blockDim.x + threadIdx.x;
    if (i < n4) {
        float4 v = ((const float4*)in)[i];
        __half2 a = __floats2half2_rn(v.x, v.y);
        __half2 b = __floats2half2_rn(v.z, v.w);
        uint2 u;
        u.x = *(uint32_t*)&a;
        u.y = *(uint32_t*)&b;
        ((uint2*)out)[i] = u;
    }
}

// ---------------- small kernels ----------------
__global__ void zero3_kernel() {
    int i = blockIdx.x * blockDim.x + threadIdx.x;
    if (i < N_NODES) {
        g_deg_out[i] = 0;
        g_deg_in[i]  = 0;
        g_fill[i]    = 0;
    }
}

__global__ void count_deg_kernel(const int* __restrict__ src, const int* __restrict__ dst) {
    int e = blockIdx.x * blockDim.x + threadIdx.x;
    if (e < N_EDGES) {
        atomicAdd(&g_deg_out[src[e]], 1);
        atomicAdd(&g_deg_in[dst[e]], 1);
    }
}

__global__ void norm_kernel() {
    int i = blockIdx.x * blockDim.x + threadIdx.x;
    if (i < N_NODES) {
        int doo = g_deg_out[i]; if (doo < 1) doo = 1;
        int din = g_deg_in[i];  if (din < 1) din = 1;
        g_nsrc[i] = rsqrtf((float)doo);
        g_ndst[i] = rsqrtf((float)din);
    }
}

// ---- 3-phase grid-wide exclusive scan of g_deg_in -> g_row_ptr ----
__global__ void scan1_kernel() {
    __shared__ int warpsum[32];
    int tid = threadIdx.x, lane = tid & 31, wid = tid >> 5;
    int i = blockIdx.x * SCAN_BLK + tid;
    int v = (i < N_NODES) ? g_deg_in[i] : 0;
    int x = v;
    #pragma unroll
    for (int off = 1; off < 32; off <<= 1) {
        int t = __shfl_up_sync(0xffffffffu, x, off);
        if (lane >= off) x += t;
    }
    if (lane == 31) warpsum[wid] = x;
    __syncthreads();
    if (wid == 0) {
        int w = warpsum[lane];
        #pragma unroll
        for (int off = 1; off < 32; off <<= 1) {
            int t = __shfl_up_sync(0xffffffffu, w, off);
            if (lane >= off) w += t;
        }
        warpsum[lane] = w;
    }
    __syncthreads();
    int offset = (wid > 0) ? warpsum[wid - 1] : 0;
    if (i < N_NODES) g_row_ptr[i] = x + offset - v;
    if (tid == SCAN_BLK - 1) g_bsum[blockIdx.x] = x + offset;
}

__global__ void scan2_kernel() {
    int lane = threadIdx.x;
    int carry = 0;
    for (int base = 0; base < SCAN_NBLK; base += 32) {
        int i = base + lane;
        int v = (i < SCAN_NBLK) ? g_bsum[i] : 0;
        int x = v;
        #pragma unroll
        for (int off = 1; off < 32; off <<= 1) {
            int t = __shfl_up_sync(0xffffffffu, x, off);
            if (lane >= off) x += t;
        }
        if (i < SCAN_NBLK) g_boff[i] = carry + x - v;
        carry += __shfl_sync(0xffffffffu, x, 31);
    }
    if (lane == 0) g_row_ptr[N_NODES] = carry;
}

__global__ void scan3_kernel() {
    int i = blockIdx.x * SCAN_BLK + threadIdx.x;
    if (i < N_NODES && blockIdx.x > 0) g_row_ptr[i] += g_boff[blockIdx.x];
}

__global__ void build_csr_kernel(const int* __restrict__ src, const int* __restrict__ dst) {
    int e = blockIdx.x * blockDim.x + threadIdx.x;
    if (e < N_EDGES) {
        int d = dst[e];
        int pos = g_row_ptr[d] + atomicAdd(&g_fill[d], 1);
        g_csr_src[pos] = src[e];
    }
}

// ---------------- fp16 tensor-core GEMM, 4-stage cp.async, static smem ---
__device__ __forceinline__ uint32_t smem_u32(const void* p) {
    return (uint32_t)__cvta_generic_to_shared(p);
}
__device__ __forceinline__ void cp_async16(uint32_t s, const void* g) {
    asm volatile("cp.async.cg.shared.global [%0], [%1], 16;\n"
        :: "r"(s), "l"(__cvta_generic_to_global(g)));
}
__device__ __forceinline__ void cp_commit() {
    asm volatile("cp.async.commit_group;\n");
}
template <int NW>
__device__ __forceinline__ void cp_wait() {
    asm volatile("cp.async.wait_group %0;\n" :: "n"(NW));
}
__device__ __forceinline__ void ldsm_x4(uint32_t* r, uint32_t addr) {
    asm volatile("ldmatrix.sync.aligned.m8n8.x4.shared.b16 {%0,%1,%2,%3}, [%4];\n"
        : "=r"(r[0]), "=r"(r[1]), "=r"(r[2]), "=r"(r[3]) : "r"(addr));
}
__device__ __forceinline__ void ldsm_x4_trans(uint32_t* r, uint32_t addr) {
    asm volatile("ldmatrix.sync.aligned.m8n8.x4.trans.shared.b16 {%0,%1,%2,%3}, [%4];\n"
        : "=r"(r[0]), "=r"(r[1]), "=r"(r[2]), "=r"(r[3]) : "r"(addr));
}
__device__ __forceinline__ void mma16816h(float* c, const uint32_t* a, const uint32_t* b) {
    asm volatile(
        "mma.sync.aligned.m16n8k16.row.col.f32.f16.f16.f32 "
        "{%0,%1,%2,%3}, {%4,%5,%6,%7}, {%8,%9}, {%0,%1,%2,%3};\n"
        : "+f"(c[0]), "+f"(c[1]), "+f"(c[2]), "+f"(c[3])
        : "r"(a[0]), "r"(a[1]), "r"(a[2]), "r"(a[3]), "r"(b[0]), "r"(b[1]));
}

#define GBM 128
#define GBK 16
#define GSTAGES 4

template <int BN, bool RELU, bool OUT16>
__global__ __launch_bounds__(256)
void gemm_f16_kernel(const __half* __restrict__ A,
                     const __half* __restrict__ B,
                     const float* __restrict__ bias,
                     float* __restrict__ Cf,
                     __half* __restrict__ C16,
                     int M, int N, int K) {
    constexpr int WN  = BN / 2;
    constexpr int NJ  = WN / 8;
    constexpr int NJP = NJ / 2;
    __shared__ __align__(16) __half As[GSTAGES][GBM][GBK + 8];
    __shared__ __align__(16) __half Bs[GSTAGES][GBK][BN + 8];

    int tid = threadIdx.x;
    int lane = tid & 31, wid = tid >> 5;
    int wm = wid & 3, wn = wid >> 2;
    int rowBase = blockIdx.y * GBM;
    int colBase = blockIdx.x * BN;

    float acc[2][NJ][4];
    #pragma unroll
    for (int i = 0; i < 2; i++)
        #pragma unroll
        for (int j = 0; j < NJ; j++)
            #pragma unroll
            for (int q = 0; q < 4; q++) acc[i][j][q] = 0.f;

    auto load_stage = [&](int s, int k0) {
        {
            int r = tid >> 1;
            int c8 = (tid & 1) << 3;
            int row = rowBase + r;
            if (row > M - 1) row = M - 1;
            cp_async16(smem_u32(&As[s][r][c8]), A + (size_t)row * K + k0 + c8);
        }
        #pragma unroll
        for (int q = tid; q < 2 * BN; q += 256) {
            int r = q / (BN / 8);
            int c8 = (q % (BN / 8)) << 3;
            cp_async16(smem_u32(&Bs[s][r][c8]), B + (size_t)(k0 + r) * N + colBase + c8);
        }
        cp_commit();
    };

    int T = K / GBK;
    load_stage(0, 0);
    load_stage(1, GBK);
    load_stage(2, 2 * GBK);

    for (int t = 0; t < T; t++) {
        cp_wait<GSTAGES - 2>();
        __syncthreads();
        int pf = t + GSTAGES - 1;
        if (pf < T) load_stage(pf % GSTAGES, pf * GBK);
        int cur = t % GSTAGES;

        uint32_t a[2][4];
        #pragma unroll
        for (int mi = 0; mi < 2; mi++) {
            int r = wm * 32 + mi * 16 + (lane & 15);
            int c = (lane >> 4) << 3;
            ldsm_x4(a[mi], smem_u32(&As[cur][r][c]));
        }
        uint32_t b[NJ][2];
        #pragma unroll
        for (int p = 0; p < NJP; p++) {
            int r = (lane & 7) + (lane & 8);
            int c = wn * WN + p * 16 + ((lane >> 4) << 3);
            uint32_t tt[4];
            ldsm_x4_trans(tt, smem_u32(&Bs[cur][r][c]));
            b[2 * p][0] = tt[0]; b[2 * p][1] = tt[1];
            b[2 * p + 1][0] = tt[2]; b[2 * p + 1][1] = tt[3];
        }
        #pragma unroll
        for (int mi = 0; mi < 2; mi++)
            #pragma unroll
            for (int nj = 0; nj < NJ; nj++)
                mma16816h(acc[mi][nj], a[mi], b[nj]);
    }

    int g = lane >> 2, tig = lane & 3;
    #pragma unroll
    for (int mi = 0; mi < 2; mi++) {
        int row0 = rowBase + wm * 32 + mi * 16 + g;
        int row1 = row0 + 8;
        #pragma unroll
        for (int nj = 0; nj < NJ; nj++) {
            int col = colBase + wn * WN + nj * 8 + 2 * tig;
            float bv0 = bias[col], bv1 = bias[col + 1];
            float v0 = acc[mi][nj][0] + bv0;
            float v1 = acc[mi][nj][1] + bv1;
            float v2 = acc[mi][nj][2] + bv0;
            float v3 = acc[mi][nj][3] + bv1;
            if (RELU) {
                v0 = fmaxf(v0, 0.f); v1 = fmaxf(v1, 0.f);
                v2 = fmaxf(v2, 0.f); v3 = fmaxf(v3, 0.f);
            }
            if (OUT16) {
                if (row0 < M) *(__half2*)&C16[(size_t)row0 * N + col] = __floats2half2_rn(v0, v1);
                if (row1 < M) *(__half2*)&C16[(size_t)row1 * N + col] = __floats2half2_rn(v2, v3);
            } else {
                if (row0 < M) {
                    Cf[(size_t)row0 * N + col]     = v0;
                    Cf[(size_t)row0 * N + col + 1] = v1;
                }
                if (row1 < M) {
                    Cf[(size_t)row1 * N + col]     = v2;
                    Cf[(size_t)row1 * N + col + 1] = v3;
                }
            }
        }
    }
}

// ------- pre-scale x0: x0s = x016 * nsrc (8 lanes/node, uint4) ------------
__global__ void scale_x0_kernel() {
    int i = blockIdx.x * blockDim.x + threadIdx.x;
    if (i >= N_NODES * 8) return;
    int node = i >> 3;
    float ns = g_nsrc[node];
    uint4 u = ((const uint4*)g_x016)[i];
    __half2* h = (__half2*)&u;
    uint4 o;
    __half2* ho = (__half2*)&o;
    #pragma unroll
    for (int q = 0; q < 4; q++) {
        float2 f = __half22float2(h[q]);
        ho[q] = __floats2half2_rn(f.x * ns, f.y * ns);
    }
    ((uint4*)g_x0s)[i] = o;
}

// ------- propagation hop: 8 lanes/node, pre-scaled input, pure gather-add -
__device__ __forceinline__ void acc8(float* a, uint4 u) {
    __half2* h = (__half2*)&u;
    #pragma unroll
    for (int q = 0; q < 4; q++) {
        float2 f = __half22float2(h[q]);
        a[2 * q]     += f.x;
        a[2 * q + 1] += f.y;
    }
}

__device__ __forceinline__ void gather_accum(const __half* __restrict__ fin_s,
                                             int beg, int end, int lane, float* a) {
    int p = beg;
    for (; p + 4 <= end; p += 4) {
        int s0 = g_csr_src[p];
        int s1 = g_csr_src[p + 1];
        int s2 = g_csr_src[p + 2];
        int s3 = g_csr_src[p + 3];
        uint4 u0 = ((const uint4*)(fin_s + (size_t)s0 * OUT_DIM))[lane];
        uint4 u1 = ((const uint4*)(fin_s + (size_t)s1 * OUT_DIM))[lane];
        uint4 u2 = ((const uint4*)(fin_s + (size_t)s2 * OUT_DIM))[lane];
        uint4 u3 = ((const uint4*)(fin_s + (size_t)s3 * OUT_DIM))[lane];
        acc8(a, u0); acc8(a, u1); acc8(a, u2); acc8(a, u3);
    }
    for (; p < end; p++) {
        int s = g_csr_src[p];
        acc8(a, ((const uint4*)(fin_s + (size_t)s * OUT_DIM))[lane]);
    }
}

__global__ void prop_kernel(const __half* __restrict__ fin_s,
                            __half* __restrict__ fout,
                            __half* __restrict__ fout_s) {
    int t = blockIdx.x * blockDim.x + threadIdx.x;
    int node = t >> 3;
    if (node >= N_NODES) return;
    int lane = t & 7;
    int beg = g_row_ptr[node], end = g_row_ptr[node + 1];
    float a[8] = {0.f, 0.f, 0.f, 0.f, 0.f, 0.f, 0.f, 0.f};
    gather_accum(fin_s, beg, end, lane, a);
    float nd = (1.f - ALPHA) * g_ndst[node];
    uint4 uz = ((const uint4*)(g_x016 + (size_t)node * OUT_DIM))[lane];
    __half2* hz = (__half2*)&uz;
    float o[8];
    #pragma unroll
    for (int q = 0; q < 4; q++) {
        float2 z = __half22float2(hz[q]);
        o[2 * q]     = a[2 * q] * nd + ALPHA * z.x;
        o[2 * q + 1] = a[2 * q + 1] * nd + ALPHA * z.y;
    }
    uint4 uo;
    __half2* ho = (__half2*)&uo;
    #pragma unroll
    for (int q = 0; q < 4; q++)
        ho[q] = __floats2half2_rn(o[2 * q], o[2 * q + 1]);
    ((uint4*)(fout + (size_t)node * OUT_DIM))[lane] = uo;
    float ns = g_nsrc[node];
    uint4 us;
    __half2* hs = (__half2*)&us;
    #pragma unroll
    for (int q = 0; q < 4; q++)
        hs[q] = __floats2half2_rn(o[2 * q] * ns, o[2 * q + 1] * ns);
    ((uint4*)(fout_s + (size_t)node * OUT_DIM))[lane] = us;
}

// ------- final hop fused with log_softmax output + attention dots ---------
__global__ void prop_final_kernel(const __half* __restrict__ fin_s,
                                  const float* __restrict__ wsrc,
                                  const float* __restrict__ wdst,
                                  float* __restrict__ out_lsm) {
    int t = blockIdx.x * blockDim.x + threadIdx.x;
    int node = t >> 3;
    if (node >= N_NODES) return;
    int lane = t & 7;
    int beg = g_row_ptr[node], end = g_row_ptr[node + 1];
    float a[8] = {0.f, 0.f, 0.f, 0.f, 0.f, 0.f, 0.f, 0.f};
    gather_accum(fin_s, beg, end, lane, a);
    float nd = (1.f - ALPHA) * g_ndst[node];
    uint4 uz = ((const uint4*)(g_x016 + (size_t)node * OUT_DIM))[lane];
    __half2* hz = (__half2*)&uz;
    float o[8];
    #pragma unroll
    for (int q = 0; q < 4; q++) {
        float2 z = __half22float2(hz[q]);
        o[2 * q]     = a[2 * q] * nd + ALPHA * z.x;
        o[2 * q + 1] = a[2 * q + 1] * nd + ALPHA * z.y;
    }

    // log_softmax over 64 features (reduce across the 8-lane octet)
    float m = o[0];
    #pragma unroll
    for (int q = 1; q < 8; q++) m = fmaxf(m, o[q]);
    #pragma unroll
    for (int off = 1; off < 8; off <<= 1)
        m = fmaxf(m, __shfl_xor_sync(0xffffffffu, m, off));
    float s = 0.f;
    #pragma unroll
    for (int q = 0; q < 8; q++) s += expf(o[q] - m);
    #pragma unroll
    for (int off = 1; off < 8; off <<= 1)
        s += __shfl_xor_sync(0xffffffffu, s, off);
    float lse = m + logf(s);
    float4 w0, w1;
    w0.x = o[0] - lse; w0.y = o[1] - lse; w0.z = o[2] - lse; w0.w = o[3] - lse;
    w1.x = o[4] - lse; w1.y = o[5] - lse; w1.z = o[6] - lse; w1.w = o[7] - lse;
    ((float4*)(out_lsm + (size_t)node * OUT_DIM))[lane * 2]     = w0;
    ((float4*)(out_lsm + (size_t)node * OUT_DIM))[lane * 2 + 1] = w1;

    // attention dots
    float4 a0 = ((const float4*)wsrc)[lane * 2];
    float4 a1 = ((const float4*)wsrc)[lane * 2 + 1];
    float4 b0 = ((const float4*)wdst)[lane * 2];
    float4 b1 = ((const float4*)wdst)[lane * 2 + 1];
    float es = o[0] * a0.x + o[1] * a0.y + o[2] * a0.z + o[3] * a0.w
             + o[4] * a1.x + o[5] * a1.y + o[6] * a1.z + o[7] * a1.w;
    float ed = o[0] * b0.x + o[1] * b0.y + o[2] * b0.z + o[3] * b0.w
             + o[4] * b1.x + o[5] * b1.y + o[6] * b1.z + o[7] * b1.w;
    #pragma unroll
    for (int off = 1; off < 8; off <<= 1) {
        es += __shfl_xor_sync(0xffffffffu, es, off);
        ed += __shfl_xor_sync(0xffffffffu, ed, off);
    }
    if (lane == 0) {
        g_es[node] = es;
        g_ed[node] = ed;
    }
}

// --------- attention phase 1: per-node max & inverse-sum (warp/node) ------
__global__ void attn1_kernel() {
    int node = (blockIdx.x * blockDim.x + threadIdx.x) >> 5;
    if (node >= N_NODES) return;
    int lane = threadIdx.x & 31;
    int beg = g_row_ptr[node], end = g_row_ptr[node + 1];
    int deg = end - beg;
    if (deg == 0) return;
    float edv = g_ed[node];

    if (deg <= 64) {
        int p0 = beg + lane, p1 = beg + 32 + lane;
        bool a0 = p0 < end, a1 = p1 < end;
        float e0 = a0 ? tanhf(g_es[g_csr_src[p0]] + edv) : -INFINITY;
        float e1 = a1 ? tanhf(g_es[g_csr_src[p1]] + edv) : -INFINITY;
        float m = fmaxf(e0, e1);
        #pragma unroll
        for (int off = 16; off; off >>= 1) m = fmaxf(m, __shfl_xor_sync(0xffffffffu, m, off));
        float s = (a0 ? expf(e0 - m) : 0.f) + (a1 ? expf(e1 - m) : 0.f);
        #pragma unroll
        for (int off = 16; off; off >>= 1) s += __shfl_xor_sync(0xffffffffu, s, off);
        if (lane == 0) {
            g_m[node] = m;
            g_is[node] = 1.f / s;
        }
        return;
    }

    float m = -INFINITY;
    for (int p = beg + lane; p < end; p += 32)
        m = fmaxf(m, tanhf(g_es[g_csr_src[p]] + edv));
    #pragma unroll
    for (int off = 16; off; off >>= 1) m = fmaxf(m, __shfl_xor_sync(0xffffffffu, m, off));
    float s = 0.f;
    for (int p = beg + lane; p < end; p += 32)
        s += expf(tanhf(g_es[g_csr_src[p]] + edv) - m);
    #pragma unroll
    for (int off = 16; off; off >>= 1) s += __shfl_xor_sync(0xffffffffu, s, off);
    if (lane == 0) {
        g_m[node] = m;
        g_is[node] = 1.f / s;
    }
}

// --------- attention phase 2: edge-parallel coalesced write ---------------
__global__ void attn2_kernel(const int* __restrict__ src, const int* __restrict__ dst,
                             float* __restrict__ attn_out) {
    int e = blockIdx.x * blockDim.x + threadIdx.x;
    if (e < N_EDGES) {
        int s = src[e];
        int d = dst[e];
        float v = tanhf(g_es[s] + g_ed[d]);
        attn_out[e] = expf(v - g_m[d]) * g_is[d];
    }
}

// ---------------- launch ----------------
extern "C" void kernel_launch(void* const* d_in, const int* in_sizes, int n_in,
                              void* d_out, int out_size) {
    const float* h   = (const float*)d_in[0];
    const int*   src = (const int*)d_in[1];
    const int*   dst = (const int*)d_in[2];
    const float* W1  = (const float*)d_in[3];
    const float* b1  = (const float*)d_in[4];
    const float* W2  = (const float*)d_in[5];
    const float* b2  = (const float*)d_in[6];
    const float* wsr = (const float*)d_in[7];
    const float* wds = (const float*)d_in[8];
    float* out = (float*)d_out;

    __half *p_h16, *p_w1, *p_w2, *p_hid16, *p_x016, *p_x0s, *p_fA, *p_fAs, *p_fB, *p_fBs;
    cudaGetSymbolAddress((void**)&p_h16, g_h16);
    cudaGetSymbolAddress((void**)&p_w1, g_w1);
    cudaGetSymbolAddress((void**)&p_w2, g_w2);
    cudaGetSymbolAddress((void**)&p_hid16, g_hid16);
    cudaGetSymbolAddress((void**)&p_x016, g_x016);
    cudaGetSymbolAddress((void**)&p_x0s, g_x0s);
    cudaGetSymbolAddress((void**)&p_fA, g_fA16);
    cudaGetSymbolAddress((void**)&p_fAs, g_fAs);
    cudaGetSymbolAddress((void**)&p_fB, g_fB16);
    cudaGetSymbolAddress((void**)&p_fBs, g_fBs);

    const int TPB = 256;
    int nodeBlocks = (N_NODES + TPB - 1) / TPB;
    int edgeBlocks = (N_EDGES + TPB - 1) / TPB;
    int warpNodeBlocks = (N_NODES * 32 + TPB - 1) / TPB;
    int octNodeBlocks = (N_NODES * 8 + TPB - 1) / TPB;

    // 1-3: zero + conversions (gemm1 kept in ncu capture slot 4)
    zero3_kernel<<<nodeBlocks, TPB>>>();
    {
        int n4 = N_NODES * IN_DIM / 4;
        f32_to_f16_kernel<<<(n4 + TPB - 1) / TPB, TPB>>>(h, p_h16, n4);
        int w4 = IN_DIM * HID_DIM / 4;
        f32_to_f16_kernel<<<(w4 + TPB - 1) / TPB, TPB>>>(W1, p_w1, w4);
    }

    // 4: GEMM1  hidden16 = fp16(relu(h @ W1 + b1)) — BN=64 tiles for occupancy
    {
        dim3 grid1(HID_DIM / 64, (N_NODES + GBM - 1) / GBM);
        gemm_f16_kernel<64, true, true><<<grid1, 256>>>(
            p_h16, p_w1, b1, nullptr, p_hid16, N_NODES, HID_DIM, IN_DIM);
    }

    {
        int w4 = HID_DIM * OUT_DIM / 4;
        f32_to_f16_kernel<<<(w4 + TPB - 1) / TPB, TPB>>>(W2, p_w2, w4);
    }
    count_deg_kernel<<<edgeBlocks, TPB>>>(src, dst);
    norm_kernel<<<nodeBlocks, TPB>>>();
    scan1_kernel<<<SCAN_NBLK, SCAN_BLK>>>();
    scan2_kernel<<<1, 32>>>();
    scan3_kernel<<<SCAN_NBLK, SCAN_BLK>>>();
    build_csr_kernel<<<edgeBlocks, TPB>>>(src, dst);

    // GEMM2  x0(fp16) = hidden @ W2 + b2, then pre-scale
    {
        dim3 grid2(OUT_DIM / 64, (N_NODES + GBM - 1) / GBM);
        gemm_f16_kernel<64, false, true><<<grid2, 256>>>(
            p_hid16, p_w2, b2, nullptr, p_x016, N_NODES, OUT_DIM, HID_DIM);
    }
    scale_x0_kernel<<<octNodeBlocks, TPB>>>();

    // K_HOPS=4 propagation; final hop fused with lsm output + dots
    prop_kernel<<<octNodeBlocks, TPB>>>(p_x0s, p_fA, p_fAs);
    prop_kernel<<<octNodeBlocks, TPB>>>(p_fAs, p_fB, p_fBs);
    prop_kernel<<<octNodeBlocks, TPB>>>(p_fBs, p_fA, p_fAs);
    prop_final_kernel<<<octNodeBlocks, TPB>>>(p_fAs, wsr, wds, out);

    // attention: per-node (m, 1/s), then edge-parallel coalesced write
    attn1_kernel<<<warpNodeBlocks, TPB>>>();
    attn2_kernel<<<edgeBlocks, TPB>>>(src, dst, out + (size_t)N_NODES * OUT_DIM);
}